// round 17
// baseline (speedup 1.0000x reference)
#include <cuda_runtime.h>
#include <cuda_bf16.h>
#include <math.h>
#include <stdint.h>

#define NQ 1024
#define TT 1024
#define DM 128
#define CH 256
#define KO 128

// ---------------- scratch (static device memory; no allocs) ----------------
__device__ float g_qkv[NQ * 384];
__device__ __nv_bfloat16 g_t1bf[TT * CH];
__device__ float g_scores[4 * NQ * NQ];
__device__ float g_ctxp[4][NQ * DM];   // split-K partials (deterministic)
__device__ float g_att[NQ * DM];
__device__ __nv_bfloat16 g_n1bf[NQ * CH];
__device__ __nv_bfloat16 g_W2bf[KO * CH];

__device__ __forceinline__ void cp16(uint32_t dst, const void* src)
{
    asm volatile("cp.async.cg.shared.global [%0], [%1], 16;" :: "r"(dst), "l"(src));
}
#define CP_COMMIT() asm volatile("cp.async.commit_group;" ::: "memory")
#define CP_WAIT0()  asm volatile("cp.async.wait_group 0;" ::: "memory")
#define CP_WAIT1()  asm volatile("cp.async.wait_group 1;" ::: "memory")

// ---------------- fused QKV + t1 projections (z selects problem) -----------
__global__ __launch_bounds__(256) void qkv_t1_kernel(
    const float* __restrict__ node, const float* __restrict__ ipw, const float* __restrict__ ipb,
    const float* __restrict__ task, const float* __restrict__ W1, const float* __restrict__ b1)
{
    __shared__ float As[16][68];
    __shared__ float Bs[16][68];
    const float *A, *B, *bias;
    int ldb;
    if (blockIdx.z == 0) { A = node; B = ipw; bias = ipb; ldb = 128; }
    else { if (blockIdx.x >= 4) return;
           A = task; B = W1; bias = b1; ldb = 256; }
    int tid = threadIdx.x, tx = tid & 15, ty = tid >> 4;
    int m0 = blockIdx.y * 64, n0 = blockIdx.x * 64;

    float acc[4][4];
#pragma unroll
    for (int i = 0; i < 4; i++)
#pragma unroll
        for (int j = 0; j < 4; j++) acc[i][j] = 0.f;

    for (int k0 = 0; k0 < 128; k0 += 16) {
#pragma unroll
        for (int it = 0; it < 4; it++) {
            int idx = tid + it * 256;
            As[idx & 15][idx >> 4] = A[(size_t)(m0 + (idx >> 4)) * 128 + k0 + (idx & 15)];
        }
#pragma unroll
        for (int it = 0; it < 4; it++) {
            int idx = tid + it * 256;
            Bs[idx & 15][idx >> 4] = B[(size_t)(n0 + (idx >> 4)) * ldb + k0 + (idx & 15)];
        }
        __syncthreads();
#pragma unroll
        for (int k = 0; k < 16; k++) {
            float4 a = *(const float4*)&As[k][ty * 4];
            float4 b = *(const float4*)&Bs[k][tx * 4];
            float av[4] = {a.x, a.y, a.z, a.w};
            float bv[4] = {b.x, b.y, b.z, b.w};
#pragma unroll
            for (int i = 0; i < 4; i++)
#pragma unroll
                for (int j = 0; j < 4; j++) acc[i][j] = fmaf(av[i], bv[j], acc[i][j]);
        }
        __syncthreads();
    }
    if (blockIdx.z == 0) {
#pragma unroll
        for (int i = 0; i < 4; i++)
#pragma unroll
            for (int j = 0; j < 4; j++) {
                int n = n0 + tx * 4 + j;
                g_qkv[(size_t)(m0 + ty * 4 + i) * 384 + n] = acc[i][j] + bias[n];
            }
    } else {
#pragma unroll
        for (int i = 0; i < 4; i++) {
            int m = m0 + ty * 4 + i;
            int n = n0 + tx * 4;
            __nv_bfloat162 lo = __floats2bfloat162_rn(acc[i][0] + bias[n],
                                                      acc[i][1] + bias[n + 1]);
            __nv_bfloat162 hi = __floats2bfloat162_rn(acc[i][2] + bias[n + 2],
                                                      acc[i][3] + bias[n + 3]);
            *(uint32_t*)&g_t1bf[(size_t)m * 256 + n] = *(uint32_t*)&lo;
            *(uint32_t*)&g_t1bf[(size_t)m * 256 + n + 2] = *(uint32_t*)&hi;
        }
    }
}

// ---------------- scores GEMM (batched over heads) --------------------------
__global__ __launch_bounds__(256) void gemm_f32b(
    const float* __restrict__ A, int lda, int sAz,
    const float* __restrict__ B, int ldb, int sBz,
    float alpha, float* __restrict__ C, int ldc, int sCz, int K)
{
    __shared__ float As[16][68];
    __shared__ float Bs[16][68];
    int tid = threadIdx.x;
    int tx = tid & 15, ty = tid >> 4;
    int m0 = blockIdx.y * 64, n0 = blockIdx.x * 64;
    int h = blockIdx.z;
    A += (size_t)h * sAz; B += (size_t)h * sBz; C += (size_t)h * sCz;

    float acc[4][4];
#pragma unroll
    for (int i = 0; i < 4; i++)
#pragma unroll
        for (int j = 0; j < 4; j++) acc[i][j] = 0.f;

    for (int k0 = 0; k0 < K; k0 += 16) {
#pragma unroll
        for (int it = 0; it < 4; it++) {
            int idx = tid + it * 256;
            int k = idx & 15, m = idx >> 4;
            As[k][m] = A[(size_t)(m0 + m) * lda + k0 + k];
        }
#pragma unroll
        for (int it = 0; it < 4; it++) {
            int idx = tid + it * 256;
            int k = idx & 15, n = idx >> 4;
            Bs[k][n] = B[(size_t)(n0 + n) * ldb + k0 + k];
        }
        __syncthreads();
#pragma unroll
        for (int k = 0; k < 16; k++) {
            float4 a = *(const float4*)&As[k][ty * 4];
            float4 b = *(const float4*)&Bs[k][tx * 4];
            float av[4] = {a.x, a.y, a.z, a.w};
            float bv[4] = {b.x, b.y, b.z, b.w};
#pragma unroll
            for (int i = 0; i < 4; i++)
#pragma unroll
                for (int j = 0; j < 4; j++) acc[i][j] = fmaf(av[i], bv[j], acc[i][j]);
        }
        __syncthreads();
    }

#pragma unroll
    for (int i = 0; i < 4; i++) {
        int m = m0 + ty * 4 + i;
#pragma unroll
        for (int j = 0; j < 4; j++) {
            int n = n0 + tx * 4 + j;
            C[(size_t)m * ldc + n] = alpha * acc[i][j];
        }
    }
}

// ------- fused softmax (4 heads per row) + head-mean + W2->bf16 -------------
__global__ __launch_bounds__(256) void softmax_fused(
    const float* __restrict__ W2, float* __restrict__ out)
{
    int row = blockIdx.x, tid = threadIdx.x;
    __shared__ float red[8];
    __shared__ float red2[8];
    float acc[4] = {0.f, 0.f, 0.f, 0.f};

#pragma unroll
    for (int h = 0; h < 4; h++) {
        float* p = g_scores + (size_t)h * 1048576 + (size_t)row * 1024;
        float v[4];
        float mx = -1e30f;
#pragma unroll
        for (int i = 0; i < 4; i++) { v[i] = p[tid + i * 256]; mx = fmaxf(mx, v[i]); }
#pragma unroll
        for (int o = 16; o; o >>= 1) mx = fmaxf(mx, __shfl_xor_sync(0xffffffffu, mx, o));
        __syncthreads();
        if ((tid & 31) == 0) red[tid >> 5] = mx;
        __syncthreads();
        float m2 = red[0];
#pragma unroll
        for (int w = 1; w < 8; w++) m2 = fmaxf(m2, red[w]);

        float s = 0.f;
#pragma unroll
        for (int i = 0; i < 4; i++) { v[i] = expf(v[i] - m2); s += v[i]; }
#pragma unroll
        for (int o = 16; o; o >>= 1) s += __shfl_xor_sync(0xffffffffu, s, o);
        if ((tid & 31) == 0) red2[tid >> 5] = s;
        __syncthreads();
        float tot = 0.f;
#pragma unroll
        for (int w = 0; w < 8; w++) tot += red2[w];
        float inv = 1.f / tot;
#pragma unroll
        for (int i = 0; i < 4; i++) {
            float pv = v[i] * inv;
            p[tid + i * 256] = pv;
            acc[i] += pv;
        }
    }
#pragma unroll
    for (int i = 0; i < 4; i++)
        out[(size_t)row * 1024 + tid + i * 256] = 0.25f * acc[i];
    if (row < 128) g_W2bf[row * 256 + tid] = __float2bfloat16(W2[row * 256 + tid]);
}

// ------- ctx kernel: g_ctxp[kc] partial of P @ V, cp.async double-buffered --
// grid (4 kc, 16 q, 4 h) = 256 CTAs. K=256/CTA in 2 prefetched sub-chunks.
#define CTX_VS (64 * 132)                 // float offset of V within buffer
#define CTX_BUF (64 * 132 + 128 * 36)     // 13056 floats per buffer
#define CTX_SMEM (2 * CTX_BUF * 4)        // 104448 bytes

__global__ __launch_bounds__(256) void ctx_kernel()
{
    extern __shared__ float cs[];
    int tid = threadIdx.x;
    int kc = blockIdx.x, q0 = blockIdx.y * 64, h = blockIdx.z;
    int lane = tid & 31, wid = tid >> 5;
    int qb = wid * 8;
    uint32_t smu = (uint32_t)__cvta_generic_to_shared(cs);

    const float* Pg = g_scores + (size_t)h * 1048576;
    const float* Vg = g_qkv + 256 + h * 32;

    // stage both sub-chunks up front (one cp.async group per sub-chunk)
#pragma unroll
    for (int sub = 0; sub < 2; sub++) {
        int k0 = kc * 256 + sub * 128;
        uint32_t base = smu + sub * CTX_BUF * 4;
#pragma unroll
        for (int j = 0; j < 8; j++) {
            int idx = tid + j * 256;
            int r = idx >> 5, c4 = idx & 31;
            cp16(base + (r * 132 + c4 * 4) * 4,
                 &Pg[(size_t)(q0 + r) * 1024 + k0 + c4 * 4]);
        }
#pragma unroll
        for (int j = 0; j < 4; j++) {
            int idx = tid + j * 256;
            int k = idx >> 3, d4 = idx & 7;
            cp16(base + (CTX_VS + k * 36 + d4 * 4) * 4,
                 &Vg[(size_t)(k0 + k) * 384 + d4 * 4]);
        }
        CP_COMMIT();
    }

    float acc[8];
#pragma unroll
    for (int i = 0; i < 8; i++) acc[i] = 0.f;

#pragma unroll
    for (int sub = 0; sub < 2; sub++) {
        if (sub == 0) { CP_WAIT1(); } else { CP_WAIT0(); }
        __syncthreads();
        const float* Pt = cs + sub * CTX_BUF;
        const float* Vs = Pt + CTX_VS;
#pragma unroll
        for (int kb = 0; kb < 32; kb++) {
            float v0 = Vs[(kb * 4 + 0) * 36 + lane];
            float v1 = Vs[(kb * 4 + 1) * 36 + lane];
            float v2 = Vs[(kb * 4 + 2) * 36 + lane];
            float v3 = Vs[(kb * 4 + 3) * 36 + lane];
#pragma unroll
            for (int q = 0; q < 8; q++) {
                float4 p = *(const float4*)&Pt[(qb + q) * 132 + kb * 4];
                acc[q] = fmaf(p.x, v0, acc[q]);
                acc[q] = fmaf(p.y, v1, acc[q]);
                acc[q] = fmaf(p.z, v2, acc[q]);
                acc[q] = fmaf(p.w, v3, acc[q]);
            }
        }
    }
    float* outp = g_ctxp[kc];
#pragma unroll
    for (int q = 0; q < 8; q++)
        outp[(size_t)(q0 + qb + q) * 128 + h * 32 + lane] = acc[q];
}

// ------- fused attended-projection + n1 + bf16 convert ----------------------
__global__ __launch_bounds__(256) void att_n1(
    const float* __restrict__ outw, const float* __restrict__ outb,
    const float* __restrict__ W1)
{
    __shared__ float As[16][68];
    __shared__ float Bs[16][132];
    __shared__ float att_s[64][133];
    int tid = threadIdx.x, tx = tid & 15, ty = tid >> 4;
    int m0 = blockIdx.y * 64, n0 = blockIdx.x * 64;

    // ---- phase 1: att = ctx @ outw^T + outb, 64 x 128 ----
    float a8[4][8];
#pragma unroll
    for (int i = 0; i < 4; i++)
#pragma unroll
        for (int j = 0; j < 8; j++) a8[i][j] = 0.f;

    for (int k0 = 0; k0 < 128; k0 += 16) {
#pragma unroll
        for (int it = 0; it < 4; it++) {
            int idx = tid + it * 256;
            size_t o = (size_t)(m0 + (idx >> 4)) * 128 + k0 + (idx & 15);
            As[idx & 15][idx >> 4] = g_ctxp[0][o] + g_ctxp[1][o] + g_ctxp[2][o] + g_ctxp[3][o];
        }
#pragma unroll
        for (int it = 0; it < 8; it++) {
            int idx = tid + it * 256;
            int n = idx & 127, k = idx >> 7;
            Bs[k][n] = outw[(size_t)n * 128 + k0 + k];
        }
        __syncthreads();
#pragma unroll
        for (int k = 0; k < 16; k++) {
            float4 a = *(const float4*)&As[k][ty * 4];
            float4 b0 = *(const float4*)&Bs[k][tx * 8];
            float4 b1 = *(const float4*)&Bs[k][tx * 8 + 4];
            float av[4] = {a.x, a.y, a.z, a.w};
            float bv[8] = {b0.x, b0.y, b0.z, b0.w, b1.x, b1.y, b1.z, b1.w};
#pragma unroll
            for (int i = 0; i < 4; i++)
#pragma unroll
                for (int j = 0; j < 8; j++) a8[i][j] = fmaf(av[i], bv[j], a8[i][j]);
        }
        __syncthreads();
    }
#pragma unroll
    for (int i = 0; i < 4; i++) {
        int m = ty * 4 + i;
#pragma unroll
        for (int j = 0; j < 8; j++) {
            int col = tx * 8 + j;
            float v = a8[i][j] + outb[col];
            att_s[m][col] = v;
            if (blockIdx.x == 0) g_att[(size_t)(m0 + m) * 128 + col] = v;
        }
    }
    __syncthreads();

    // ---- phase 2: n1 = att @ W1[:,128:]^T, 64 x 64 chunk -> bf16 ----
    float c2[4][4];
#pragma unroll
    for (int i = 0; i < 4; i++)
#pragma unroll
        for (int j = 0; j < 4; j++) c2[i][j] = 0.f;

    for (int k0 = 0; k0 < 128; k0 += 16) {
#pragma unroll
        for (int it = 0; it < 4; it++) {
            int idx = tid + it * 256;
            As[idx & 15][idx >> 4] = W1[(size_t)(n0 + (idx >> 4)) * 256 + 128 + k0 + (idx & 15)];
        }
        __syncthreads();
#pragma unroll
        for (int k = 0; k < 16; k++) {
            float4 b = *(const float4*)&As[k][tx * 4];
            float bv[4] = {b.x, b.y, b.z, b.w};
#pragma unroll
            for (int i = 0; i < 4; i++) {
                float av = att_s[ty * 4 + i][k0 + k];
#pragma unroll
                for (int j = 0; j < 4; j++) c2[i][j] = fmaf(av, bv[j], c2[i][j]);
            }
        }
        __syncthreads();
    }
#pragma unroll
    for (int i = 0; i < 4; i++) {
        int m = m0 + ty * 4 + i;
        __nv_bfloat162 lo = __floats2bfloat162_rn(c2[i][0], c2[i][1]);
        __nv_bfloat162 hi = __floats2bfloat162_rn(c2[i][2], c2[i][3]);
        *(uint32_t*)&g_n1bf[(size_t)m * 256 + n0 + tx * 4] = *(uint32_t*)&lo;
        *(uint32_t*)&g_n1bf[(size_t)m * 256 + n0 + tx * 4 + 2] = *(uint32_t*)&hi;
    }
}

// ============== persistent pairwise MLP (34.4 GMAC, bf16 mma.sync) ==========
// CTA GRID_MATCH-1 (a 53-tile CTA) also computes the coordination head first.
#define GRID_MATCH 152
#define NTILES 8192

#define SM_A 0
#define SM_B 67584
#define SM_T1_0 135168
#define SM_T1_1 139264
#define SM_N1_0 143360
#define SM_N1_1 151808
#define SM_W3 160256
#define SM_B2 160768
#define SM_ZP 161280
#define SMEM_TOTAL 162304
#define ROWSTRIDE_B 528
#define N1STRIDE 528

__device__ __forceinline__ void ldm_x4(uint32_t& r0, uint32_t& r1, uint32_t& r2, uint32_t& r3,
                                       uint32_t addr)
{
    asm volatile("ldmatrix.sync.aligned.m8n8.x4.shared.b16 {%0,%1,%2,%3}, [%4];"
                 : "=r"(r0), "=r"(r1), "=r"(r2), "=r"(r3)
                 : "r"(addr));
}

__device__ __forceinline__ void mma_bf16(float& c0, float& c1, float& c2, float& c3,
                                         uint32_t a0, uint32_t a1, uint32_t a2, uint32_t a3,
                                         uint32_t b0, uint32_t b1)
{
    asm volatile(
        "mma.sync.aligned.m16n8k16.row.col.f32.bf16.bf16.f32 "
        "{%0,%1,%2,%3}, {%4,%5,%6,%7}, {%8,%9}, {%0,%1,%2,%3};"
        : "+f"(c0), "+f"(c1), "+f"(c2), "+f"(c3)
        : "r"(a0), "r"(a1), "r"(a2), "r"(a3), "r"(b0), "r"(b1));
}

// packed bf16x2 relu(a + b)
__device__ __forceinline__ uint32_t hrelu2(uint32_t a, uint32_t b)
{
    __nv_bfloat162 z = __float2bfloat162_rn(0.f);
    __nv_bfloat162 s = __hadd2(*reinterpret_cast<__nv_bfloat162*>(&a),
                               *reinterpret_cast<__nv_bfloat162*>(&b));
    s = __hmax2(s, z);
    return *reinterpret_cast<uint32_t*>(&s);
}

__global__ __launch_bounds__(256, 1) void match_kernel(
    const float* __restrict__ W3, const float* __restrict__ b2v,
    const float* __restrict__ b3,
    const float* __restrict__ Wc1, const float* __restrict__ bc1,
    const float* __restrict__ Wc2, const float* __restrict__ bc2,
    float* __restrict__ out)
{
    extern __shared__ char sm[];
    float* sW3 = (float*)(sm + SM_W3);
    float* sb2 = (float*)(sm + SM_B2);
    float* zpart = (float*)(sm + SM_ZP);

    int tid = threadIdx.x;
    int lane = tid & 31, wid = tid >> 5;
    int wm = wid >> 1, wn = wid & 1;

    const int t1Off[2] = {SM_T1_0, SM_T1_1};
    const int n1Off[2] = {SM_N1_0, SM_N1_1};
    uint32_t smuBase = (uint32_t)__cvta_generic_to_shared(sm);

    // ---- coordination head on the last (53-tile) CTA, using SM_A scratch ----
    if (blockIdx.x == GRID_MATCH - 1) {
        float* ps = (float*)(sm + SM_A);
        float* gs = ps + 256;
        float* hh = gs + 128;
        int d = tid & 127, half = tid >> 7;
        float s = 0.f;
        for (int r = half * 512; r < half * 512 + 512; r++) s += g_att[r * 128 + d];
        ps[tid] = s;
        __syncthreads();
        if (tid < 128) gs[tid] = (ps[tid] + ps[tid + 128]) * (1.f / 1024.f);
        __syncthreads();
        float hv = bc1[tid];
        for (int c = 0; c < 128; c++) hv = fmaf(gs[c], Wc1[tid * 128 + c], hv);
        hh[tid] = fmaxf(hv, 0.f);
        __syncthreads();
        if (tid < 32) {
            float z = bc2[tid];
            for (int c = 0; c < 256; c++) z = fmaf(hh[c], Wc2[tid * 256 + c], z);
            out[1048576 + tid] = z;
        }
        __syncthreads();
    }

    // ---- one-time staging: W2, W3, b2 ----
    {
        const uint4* bsrc = (const uint4*)g_W2bf;
#pragma unroll
        for (int j = 0; j < 16; j++) {
            int i = tid + j * 256;
            int r = i >> 5, q = i & 31;
            *(uint4*)(sm + SM_B + r * ROWSTRIDE_B + q * 16) = bsrc[i];
        }
        if (tid < 128) { sW3[tid] = W3[tid]; sb2[tid] = b2v[tid]; }
    }
    float b3v = b3[0];

    uint32_t aSm = (uint32_t)__cvta_generic_to_shared(sm + SM_A);
    uint32_t bSm = (uint32_t)__cvta_generic_to_shared(sm + SM_B);

    uint32_t aBase[2];
#pragma unroll
    for (int mt = 0; mt < 2; mt++) {
        int row = wm * 32 + mt * 16 + (lane & 15);
        int colb = ((lane >> 4) << 3) * 2;
        aBase[mt] = aSm + row * ROWSTRIDE_B + colb;
    }
    uint32_t bBase[4];
#pragma unroll
    for (int nt2 = 0; nt2 < 4; nt2++) {
        int nrow = wn * 64 + nt2 * 16 + ((lane >> 4) << 3) + (lane & 7);
        int kb = (((lane >> 3) & 1) << 3) * 2;
        bBase[nt2] = bSm + nrow * ROWSTRIDE_B + kb;
    }
    __syncthreads();

    int firstTile = blockIdx.x;
    if (firstTile < NTILES) {
        int t0 = (firstTile >> 6) * 8, n0 = (firstTile & 63) * 16;
        const uint4* ts = (const uint4*)(g_t1bf + (size_t)t0 * 256);
        const uint4* ns = (const uint4*)(g_n1bf + (size_t)n0 * 256);
        cp16(smuBase + SM_T1_0 + tid * 16, ts + tid);
        {
            int i0 = tid, i1 = tid + 256;
            cp16(smuBase + SM_N1_0 + (i0 >> 5) * N1STRIDE + (i0 & 31) * 16, ns + i0);
            cp16(smuBase + SM_N1_0 + (i1 >> 5) * N1STRIDE + (i1 & 31) * 16, ns + i1);
        }
        CP_COMMIT();
    }

    int bi = 0;
    for (int tile = firstTile; tile < NTILES; tile += GRID_MATCH, bi ^= 1) {
        int n0 = (tile & 63) * 16, t0 = (tile >> 6) * 8;

        CP_WAIT0();
        __syncthreads();

        // ---- build A[r] = relu_bf16(t1[r/16] + n1[r%16]) via HADD2/HMAX2 ----
        {
            const char* t1b = sm + t1Off[bi];
            const char* n1b = sm + n1Off[bi];
            int r = tid & 127, qp = tid >> 7;
            int tl = r >> 4, nl = r & 15;
            const char* t1row = t1b + tl * 512;
            const char* n1row = n1b + nl * N1STRIDE;
            char* aRow = sm + SM_A + r * ROWSTRIDE_B;
#pragma unroll
            for (int j = 0; j < 16; j++) {
                int q = qp + 2 * j;
                uint4 tv = *(const uint4*)(t1row + q * 16);
                uint4 nv = *(const uint4*)(n1row + q * 16);
                uint4 o;
                o.x = hrelu2(tv.x, nv.x);
                o.y = hrelu2(tv.y, nv.y);
                o.z = hrelu2(tv.z, nv.z);
                o.w = hrelu2(tv.w, nv.w);
                *(uint4*)(aRow + q * 16) = o;
            }
        }
        __syncthreads();

        int nextTile = tile + GRID_MATCH;
        if (nextTile < NTILES) {
            int nt0 = (nextTile >> 6) * 8, nn0 = (nextTile & 63) * 16;
            const uint4* ts = (const uint4*)(g_t1bf + (size_t)nt0 * 256);
            const uint4* ns = (const uint4*)(g_n1bf + (size_t)nn0 * 256);
            int tb = t1Off[bi ^ 1], nb = n1Off[bi ^ 1];
            cp16(smuBase + tb + tid * 16, ts + tid);
            int i0 = tid, i1 = tid + 256;
            cp16(smuBase + nb + (i0 >> 5) * N1STRIDE + (i0 & 31) * 16, ns + i0);
            cp16(smuBase + nb + (i1 >> 5) * N1STRIDE + (i1 & 31) * 16, ns + i1);
        }
        CP_COMMIT();

        float c[2][8][4];
#pragma unroll
        for (int mt = 0; mt < 2; mt++)
#pragma unroll
            for (int nt = 0; nt < 8; nt++)
#pragma unroll
                for (int j = 0; j < 4; j++) c[mt][nt][j] = 0.f;

        uint32_t a[2][2][4];
        uint32_t b[2][8][2];
#pragma unroll
        for (int mt = 0; mt < 2; mt++)
            ldm_x4(a[0][mt][0], a[0][mt][1], a[0][mt][2], a[0][mt][3], aBase[mt]);
#pragma unroll
        for (int nt2 = 0; nt2 < 4; nt2++) {
            uint32_t r0, r1, r2, r3;
            ldm_x4(r0, r1, r2, r3, bBase[nt2]);
            b[0][2 * nt2][0] = r0; b[0][2 * nt2][1] = r1;
            b[0][2 * nt2 + 1][0] = r2; b[0][2 * nt2 + 1][1] = r3;
        }

#pragma unroll
        for (int kk = 0; kk < 16; kk++) {
            int cur = kk & 1, nxt = cur ^ 1;
            if (kk < 15) {
                int ko = (kk + 1) * 32;
#pragma unroll
                for (int mt = 0; mt < 2; mt++)
                    ldm_x4(a[nxt][mt][0], a[nxt][mt][1], a[nxt][mt][2], a[nxt][mt][3],
                           aBase[mt] + ko);
#pragma unroll
                for (int nt2 = 0; nt2 < 4; nt2++) {
                    uint32_t r0, r1, r2, r3;
                    ldm_x4(r0, r1, r2, r3, bBase[nt2] + ko);
                    b[nxt][2 * nt2][0] = r0; b[nxt][2 * nt2][1] = r1;
                    b[nxt][2 * nt2 + 1][0] = r2; b[nxt][2 * nt2 + 1][1] = r3;
                }
            }
#pragma unroll
            for (int mt = 0; mt < 2; mt++)
#pragma unroll
                for (int nt = 0; nt < 8; nt++)
                    mma_bf16(c[mt][nt][0], c[mt][nt][1], c[mt][nt][2], c[mt][nt][3],
                             a[cur][mt][0], a[cur][mt][1], a[cur][mt][2], a[cur][mt][3],
                             b[cur][nt][0], b[cur][nt][1]);
        }

        int g = lane >> 2, q = lane & 3;
#pragma unroll
        for (int mt = 0; mt < 2; mt++) {
            float p0 = 0.f, p1 = 0.f;
#pragma unroll
            for (int nt = 0; nt < 8; nt++) {
                int col = wn * 64 + nt * 8 + q * 2;
                float w0 = sW3[col], w1 = sW3[col + 1];
                float bb0 = sb2[col], bb1 = sb2[col + 1];
                p0 += fmaxf(c[mt][nt][0] + bb0, 0.f) * w0 + fmaxf(c[mt][nt][1] + bb1, 0.f) * w1;
                p1 += fmaxf(c[mt][nt][2] + bb0, 0.f) * w0 + fmaxf(c[mt][nt][3] + bb1, 0.f) * w1;
            }
            p0 += __shfl_xor_sync(0xffffffffu, p0, 1);
            p0 += __shfl_xor_sync(0xffffffffu, p0, 2);
            p1 += __shfl_xor_sync(0xffffffffu, p1, 1);
            p1 += __shfl_xor_sync(0xffffffffu, p1, 2);
            if (q == 0) {
                int rA = wm * 32 + mt * 16 + g;
                zpart[rA * 2 + wn] = p0;
                zpart[(rA + 8) * 2 + wn] = p1;
            }
        }
        __syncthreads();
        if (tid < 128) {
            float z = zpart[tid * 2] + zpart[tid * 2 + 1] + b3v;
            float s = 1.f / (1.f + expf(-z));
            int t = t0 + (tid >> 4), n = n0 + (tid & 15);
            out[(size_t)t * 1024 + n] = s;
        }
        __syncthreads();
    }
}

// ---------------- launch ---------------------------------------------------
extern "C" void kernel_launch(void* const* d_in, const int* in_sizes, int n_in,
                              void* d_out, int out_size)
{
    const float* node = (const float*)d_in[0];
    const float* task = (const float*)d_in[1];
    const float* ipw  = (const float*)d_in[2];
    const float* ipb  = (const float*)d_in[3];
    const float* outw = (const float*)d_in[4];
    const float* outb = (const float*)d_in[5];
    const float* W1   = (const float*)d_in[6];
    const float* b1   = (const float*)d_in[7];
    const float* W2   = (const float*)d_in[8];
    const float* b2   = (const float*)d_in[9];
    const float* W3   = (const float*)d_in[10];
    const float* b3   = (const float*)d_in[11];
    const float* Wc1  = (const float*)d_in[12];
    const float* bc1  = (const float*)d_in[13];
    const float* Wc2  = (const float*)d_in[14];
    const float* bc2  = (const float*)d_in[15];
    float* out = (float*)d_out;

    float *qkv, *scores;
    cudaGetSymbolAddress((void**)&qkv, g_qkv);
    cudaGetSymbolAddress((void**)&scores, g_scores);

    // 0: QKV + t1 (bf16) fused
    qkv_t1_kernel<<<dim3(6, 16, 2), 256>>>(node, ipw, ipb, task, W1, b1);
    // 1: scores (all 4 heads)
    gemm_f32b<<<dim3(16, 16, 4), 256>>>(qkv, 384, 32, qkv + 128, 384, 32,
                                        0.17677669529663687f, scores, 1024, 1048576, 32);
    // 2: softmax + head-mean + W2->bf16
    softmax_fused<<<1024, 256>>>(W2, out + 1048608);
    // 3: ctx partials (deterministic split-K x4, cp.async double-buffered)
    cudaFuncSetAttribute(ctx_kernel, cudaFuncAttributeMaxDynamicSharedMemorySize, CTX_SMEM);
    ctx_kernel<<<dim3(4, 16, 4), 256, CTX_SMEM>>>();
    // 4: attended projection (sums partials) + n1 (bf16) fused
    att_n1<<<dim3(4, 16), 256>>>(outw, outb, W1);
    // 5: persistent bf16 HMMA pairwise MLP + coordination head (CTA 151)
    cudaFuncSetAttribute(match_kernel, cudaFuncAttributeMaxDynamicSharedMemorySize, SMEM_TOTAL);
    match_kernel<<<GRID_MATCH, 256, SMEM_TOTAL>>>(W3, b2, b3, Wc1, bc1, Wc2, bc2, out);
}